// round 12
// baseline (speedup 1.0000x reference)
#include <cuda_runtime.h>
#include <cuda_bf16.h>
#include <math.h>

// Problem constants
#define Bc   1024
#define Lc   8
#define Ec   256
#define Rc   10000
#define RP1  10001
#define G4   1024       // 4*E
#define ECC  512        // 2*E

// legacy 128x128 tile config (k_gates)
#define BM 128
#define BN 128
#define BK 8
#define PAD 132

// f32x2 big-tile config (k_fc2x2 / k_nn2)
#define TBM 256
#define TBN 128
#define TBK 8
#define PADA 260        // 256+4, %4==0 for 16B-aligned ulonglong2 loads
#define PADB 132        // 128+4

#define NSPLIT 37       // split-K for NN gemm -> grid 2*4*37 = 296 = 2 full waves

// ---------------- scratch (device globals; no runtime allocation) ----------------
__device__ float g_x   [Bc * Lc * Ec];
__device__ float g_h   [Bc * Ec];
__device__ float g_c   [Bc * Ec];
__device__ float g_gates[Bc * G4];
__device__ float g_hid [Bc * Lc * Ec];
__device__ float g_ec  [Bc * ECC];
__device__ float g_h1  [Bc * Ec];
__device__ float g_sf  [Bc * RP1];
__device__ float g_part[NSPLIT * Bc * Ec];
__device__ float g_bias[G4];

// ---------------- f32x2 helpers ----------------
__device__ __forceinline__ unsigned long long pack2(float x) {
    unsigned long long r;
    asm("mov.b64 %0, {%1, %1};" : "=l"(r) : "f"(x));
    return r;
}
__device__ __forceinline__ void ffma2(unsigned long long& acc,
                                      unsigned long long a,
                                      unsigned long long b) {
    asm("fma.rn.f32x2 %0, %1, %2, %0;" : "+l"(acc) : "l"(a), "l"(b));
}

// ---------------- small kernels ----------------
__global__ void k_embed(const int* __restrict__ bodys, const float* __restrict__ emb_w) {
    int idx = blockIdx.x * 256 + threadIdx.x;
    if (idx < Bc * Lc * Ec) {
        int e  = idx & (Ec - 1);
        int bl = idx >> 8;
        g_x[idx] = emb_w[bodys[bl] * Ec + e];
    }
}

__global__ void k_init(const float* __restrict__ b_ih, const float* __restrict__ b_hh) {
    int idx = blockIdx.x * 256 + threadIdx.x;
    if (idx < G4) g_bias[idx] = b_ih[idx] + b_hh[idx];
    if (idx < Bc * Ec) { g_h[idx] = 0.f; g_c[idx] = 0.f; }
}

__global__ void k_lstm_point(int t) {
    int idx = blockIdx.x * 256 + threadIdx.x;
    if (idx >= Bc * Ec) return;
    int b = idx >> 8, j = idx & (Ec - 1);
    const float* g = &g_gates[b * G4];
    float ig = 1.f / (1.f + __expf(-g[j]));
    float fg = 1.f / (1.f + __expf(-g[j + Ec]));
    float gg = tanhf(g[j + 2 * Ec]);
    float og = 1.f / (1.f + __expf(-g[j + 3 * Ec]));
    float c  = fg * g_c[idx] + ig * gg;
    float h  = og * tanhf(c);
    g_c[idx] = c;
    g_h[idx] = h;
    g_hid[(b * Lc + t) * Ec + j] = h;
}

__global__ void k_ec0() {
    int idx = blockIdx.x * 256 + threadIdx.x;
    if (idx >= Bc * Ec) return;
    int b = idx >> 8, e = idx & (Ec - 1);
    g_ec[b * ECC + e]      = g_x[(b * Lc + 0) * Ec + e];
    g_ec[b * ECC + Ec + e] = g_x[(b * Lc + 1) * Ec + e];
}

__global__ void k_ec_second(const float* __restrict__ emb_w, int i) {
    int idx = blockIdx.x * 256 + threadIdx.x;
    if (idx >= Bc * Ec) return;
    int b = idx >> 8, e = idx & (Ec - 1);
    g_ec[b * ECC + Ec + e] = emb_w[(i + 1) * Ec + e];
}

__global__ void k_nn_reduce(int i) {
    int idx = blockIdx.x * 256 + threadIdx.x;
    if (idx >= Bc * Ec) return;
    int b = idx >> 8, e = idx & (Ec - 1);
    float v = 0.f;
    #pragma unroll
    for (int s = 0; s < NSPLIT; s++) v += g_part[s * (Bc * Ec) + idx];
    v += g_sf[b * RP1 + Rc] * g_hid[(b * Lc + i) * Ec + e];
    g_ec[b * ECC + e] = v;
}

__global__ void k_copy_ec(float* __restrict__ out, int out_size) {
    int idx = blockIdx.x * 256 + threadIdx.x;
    if (idx >= Bc * ECC) return;
    int dst = Bc * RP1 + idx;
    if (dst < out_size) out[dst] = g_ec[idx];
}

// ============ f32x2 256x128x8 double-buffered NT GEMM: fc2 ============
// out[m,n] = sum_k g_h1[m,k] * W[n,k] + bias[n], N = RP1 (edge-guarded)
__global__ void __launch_bounds__(256, 1)
k_fc2x2(const float* __restrict__ W, const float* __restrict__ bias,
        float* __restrict__ out)
{
    __shared__ __align__(16) float As[2][TBK][PADA];   // [k][m]
    __shared__ __align__(16) float Bs[2][TBK][PADB];   // [k][n]

    int tid = threadIdx.x;
    int m0  = blockIdx.y * TBM, n0 = blockIdx.x * TBN;
    int tx  = tid & 15, ty = tid >> 4;

    const float* Arow = &g_h1[(m0 + tid) * Ec];
    int bn  = n0 + (tid >> 1);
    int bkq = (tid & 1) * 4;
    const int NK = Ec / TBK;                           // 32

    float4 pa0 = *(const float4*)&Arow[0];
    float4 pa1 = *(const float4*)&Arow[4];
    float4 pbv = (bn < RP1) ? *(const float4*)&W[bn * Ec + bkq]
                            : make_float4(0.f, 0.f, 0.f, 0.f);

    As[0][0][tid] = pa0.x; As[0][1][tid] = pa0.y;
    As[0][2][tid] = pa0.z; As[0][3][tid] = pa0.w;
    As[0][4][tid] = pa1.x; As[0][5][tid] = pa1.y;
    As[0][6][tid] = pa1.z; As[0][7][tid] = pa1.w;
    Bs[0][bkq + 0][tid >> 1] = pbv.x; Bs[0][bkq + 1][tid >> 1] = pbv.y;
    Bs[0][bkq + 2][tid >> 1] = pbv.z; Bs[0][bkq + 3][tid >> 1] = pbv.w;
    __syncthreads();

    unsigned long long accp[8][8] = {};
    int buf = 0;
    for (int kt = 0; kt < NK; kt++) {
        if (kt + 1 < NK) {
            int k0 = (kt + 1) * TBK;
            pa0 = *(const float4*)&Arow[k0];
            pa1 = *(const float4*)&Arow[k0 + 4];
            pbv = (bn < RP1) ? *(const float4*)&W[bn * Ec + k0 + bkq]
                             : make_float4(0.f, 0.f, 0.f, 0.f);
        }
        #pragma unroll
        for (int kk = 0; kk < TBK; kk++) {
            ulonglong2 a01 = *(const ulonglong2*)&As[buf][kk][ty * 16];
            ulonglong2 a23 = *(const ulonglong2*)&As[buf][kk][ty * 16 + 4];
            ulonglong2 a45 = *(const ulonglong2*)&As[buf][kk][ty * 16 + 8];
            ulonglong2 a67 = *(const ulonglong2*)&As[buf][kk][ty * 16 + 12];
            float4 b0 = *(const float4*)&Bs[buf][kk][tx * 8];
            float4 b1 = *(const float4*)&Bs[buf][kk][tx * 8 + 4];
            unsigned long long ap[8] = { a01.x, a01.y, a23.x, a23.y,
                                         a45.x, a45.y, a67.x, a67.y };
            unsigned long long bb[8] = { pack2(b0.x), pack2(b0.y), pack2(b0.z), pack2(b0.w),
                                         pack2(b1.x), pack2(b1.y), pack2(b1.z), pack2(b1.w) };
            #pragma unroll
            for (int i = 0; i < 8; i++)
                #pragma unroll
                for (int j = 0; j < 8; j++)
                    ffma2(accp[i][j], ap[i], bb[j]);
        }
        if (kt + 1 < NK) {
            int nb = buf ^ 1;
            As[nb][0][tid] = pa0.x; As[nb][1][tid] = pa0.y;
            As[nb][2][tid] = pa0.z; As[nb][3][tid] = pa0.w;
            As[nb][4][tid] = pa1.x; As[nb][5][tid] = pa1.y;
            As[nb][6][tid] = pa1.z; As[nb][7][tid] = pa1.w;
            Bs[nb][bkq + 0][tid >> 1] = pbv.x; Bs[nb][bkq + 1][tid >> 1] = pbv.y;
            Bs[nb][bkq + 2][tid >> 1] = pbv.z; Bs[nb][bkq + 3][tid >> 1] = pbv.w;
        }
        __syncthreads();
        buf ^= 1;
    }

    float bs[8];
    #pragma unroll
    for (int j = 0; j < 8; j++) {
        int n = n0 + tx * 8 + j;
        bs[j] = (n < RP1) ? bias[n] : 0.f;
    }
    #pragma unroll
    for (int q = 0; q < 8; q++) {
        int me = m0 + ty * 16 + 2 * q;
        #pragma unroll
        for (int j = 0; j < 8; j++) {
            int n = n0 + tx * 8 + j;
            if (n < RP1) {
                float2 v = *(float2*)&accp[q][j];
                out[me * RP1 + n]       = v.x + bs[j];
                out[(me + 1) * RP1 + n] = v.y + bs[j];
            }
        }
    }
}

// ============ f32x2 256x128x8 split-K NN GEMM ============
// part[s][m,n] = sum_{k in split s} g_sf[m,k] * emb_w[k,n]; M=1024,N=256,K=10000
__global__ void __launch_bounds__(256, 1)
k_nn2(const float* __restrict__ emb_w)
{
    __shared__ __align__(16) float As[2][TBK][PADA];
    __shared__ __align__(16) float Bs[2][TBK][PADB];

    int tid = threadIdx.x;
    int n0  = blockIdx.x * TBN, m0 = blockIdx.y * TBM, sid = blockIdx.z;
    int tx  = tid & 15, ty = tid >> 4;

    const int KT_TOT = Rc / TBK;                          // 1250
    const int PER    = (KT_TOT + NSPLIT - 1) / NSPLIT;    // 34
    int kt0 = sid * PER;
    int kt1 = min(KT_TOT, kt0 + PER);

    const float* Ar = &g_sf[(m0 + tid) * RP1];            // odd stride -> scalar
    int bkr = tid >> 5;                                   // 0..7
    int bnc = (tid & 31) * 4;                             // 0..124

    float pa[8]; float4 pbv;
    {
        int k0 = kt0 * TBK;
        #pragma unroll
        for (int q = 0; q < 8; q++) pa[q] = Ar[k0 + q];
        pbv = *(const float4*)&emb_w[(k0 + bkr) * Ec + n0 + bnc];
    }
    #pragma unroll
    for (int q = 0; q < 8; q++) As[0][q][tid] = pa[q];
    *(float4*)&Bs[0][bkr][bnc] = pbv;
    __syncthreads();

    unsigned long long accp[8][8] = {};
    int buf = 0;
    for (int kt = kt0; kt < kt1; kt++) {
        if (kt + 1 < kt1) {
            int k0 = (kt + 1) * TBK;
            #pragma unroll
            for (int q = 0; q < 8; q++) pa[q] = Ar[k0 + q];
            pbv = *(const float4*)&emb_w[(k0 + bkr) * Ec + n0 + bnc];
        }
        #pragma unroll
        for (int kk = 0; kk < TBK; kk++) {
            ulonglong2 a01 = *(const ulonglong2*)&As[buf][kk][ty * 16];
            ulonglong2 a23 = *(const ulonglong2*)&As[buf][kk][ty * 16 + 4];
            ulonglong2 a45 = *(const ulonglong2*)&As[buf][kk][ty * 16 + 8];
            ulonglong2 a67 = *(const ulonglong2*)&As[buf][kk][ty * 16 + 12];
            float4 b0 = *(const float4*)&Bs[buf][kk][tx * 8];
            float4 b1 = *(const float4*)&Bs[buf][kk][tx * 8 + 4];
            unsigned long long ap[8] = { a01.x, a01.y, a23.x, a23.y,
                                         a45.x, a45.y, a67.x, a67.y };
            unsigned long long bb[8] = { pack2(b0.x), pack2(b0.y), pack2(b0.z), pack2(b0.w),
                                         pack2(b1.x), pack2(b1.y), pack2(b1.z), pack2(b1.w) };
            #pragma unroll
            for (int i = 0; i < 8; i++)
                #pragma unroll
                for (int j = 0; j < 8; j++)
                    ffma2(accp[i][j], ap[i], bb[j]);
        }
        if (kt + 1 < kt1) {
            int nb = buf ^ 1;
            #pragma unroll
            for (int q = 0; q < 8; q++) As[nb][q][tid] = pa[q];
            *(float4*)&Bs[nb][bkr][bnc] = pbv;
        }
        __syncthreads();
        buf ^= 1;
    }

    float* P = &g_part[sid * (Bc * Ec)];
    #pragma unroll
    for (int q = 0; q < 8; q++) {
        int me = m0 + ty * 16 + 2 * q;
        #pragma unroll
        for (int j = 0; j < 8; j++) {
            int n = n0 + tx * 8 + j;
            float2 v = *(float2*)&accp[q][j];
            P[me * Ec + n]       = v.x;
            P[(me + 1) * Ec + n] = v.y;
        }
    }
}

// ---------- Fused LSTM gates (proven R8 kernel, 128x128x8 fp32) ----------
__global__ void __launch_bounds__(256)
k_gates(int t, const float* __restrict__ w_ih, const float* __restrict__ w_hh)
{
    __shared__ float As[2][BK][PAD];
    __shared__ float Bs[2][BK][PAD];

    int tid  = threadIdx.x;
    int m0   = blockIdx.y * BM, n0 = blockIdx.x * BN;
    int arow = tid >> 1;
    int ac4  = (tid & 1) * 4;
    int tx   = tid & 15, ty = tid >> 4;

    const int NK = (2 * Ec) / BK;       // 64

    auto fetch = [&](int kt, float4& pa, float4& pb) {
        if (kt < 32) {
            int k0 = kt * BK;
            pa = *(const float4*)&g_x[(m0 + arow) * (Lc * Ec) + t * Ec + k0 + ac4];
            pb = *(const float4*)&w_ih[(n0 + arow) * Ec + k0 + ac4];
        } else {
            int k0 = (kt - 32) * BK;
            pa = *(const float4*)&g_h[(m0 + arow) * Ec + k0 + ac4];
            pb = *(const float4*)&w_hh[(n0 + arow) * Ec + k0 + ac4];
        }
    };

    float4 pa, pb;
    fetch(0, pa, pb);
    As[0][ac4 + 0][arow] = pa.x; As[0][ac4 + 1][arow] = pa.y;
    As[0][ac4 + 2][arow] = pa.z; As[0][ac4 + 3][arow] = pa.w;
    Bs[0][ac4 + 0][arow] = pb.x; Bs[0][ac4 + 1][arow] = pb.y;
    Bs[0][ac4 + 2][arow] = pb.z; Bs[0][ac4 + 3][arow] = pb.w;
    __syncthreads();

    float acc[8][8] = {};
    int buf = 0;
    for (int kt = 0; kt < NK; kt++) {
        if (kt + 1 < NK) fetch(kt + 1, pa, pb);
        #pragma unroll
        for (int kk = 0; kk < BK; kk++) {
            float a[8], b[8];
            *(float4*)&a[0] = *(const float4*)&As[buf][kk][ty * 8];
            *(float4*)&a[4] = *(const float4*)&As[buf][kk][ty * 8 + 4];
            *(float4*)&b[0] = *(const float4*)&Bs[buf][kk][tx * 8];
            *(float4*)&b[4] = *(const float4*)&Bs[buf][kk][tx * 8 + 4];
            #pragma unroll
            for (int i = 0; i < 8; i++)
                #pragma unroll
                for (int j = 0; j < 8; j++)
                    acc[i][j] = fmaf(a[i], b[j], acc[i][j]);
        }
        if (kt + 1 < NK) {
            int nb = buf ^ 1;
            As[nb][ac4 + 0][arow] = pa.x; As[nb][ac4 + 1][arow] = pa.y;
            As[nb][ac4 + 2][arow] = pa.z; As[nb][ac4 + 3][arow] = pa.w;
            Bs[nb][ac4 + 0][arow] = pb.x; Bs[nb][ac4 + 1][arow] = pb.y;
            Bs[nb][ac4 + 2][arow] = pb.z; Bs[nb][ac4 + 3][arow] = pb.w;
        }
        __syncthreads();
        buf ^= 1;
    }

    #pragma unroll
    for (int i = 0; i < 8; i++) {
        int m = m0 + ty * 8 + i;
        #pragma unroll
        for (int j = 0; j < 8; j++) {
            int n = n0 + tx * 8 + j;
            g_gates[m * G4 + n] = acc[i][j] + g_bias[n];
        }
    }
}

// ---------------- fc1: 64x64x16 NT GEMM (small) ----------------
__global__ void __launch_bounds__(256)
k_fc1(const float* __restrict__ W, const float* __restrict__ bias)
{
    __shared__ float As[16][64];
    __shared__ float Bs[16][64];

    int tid = threadIdx.x;
    int tx = tid & 15, ty = tid >> 4;
    int m0 = blockIdx.y * 64, n0 = blockIdx.x * 64;

    int lm = tid >> 2;
    int lk = (tid & 3) * 4;

    float acc[4][4] = {};

    for (int k0 = 0; k0 < ECC; k0 += 16) {
        float4 av = *(const float4*)&g_ec[(m0 + lm) * ECC + k0 + lk];
        As[lk + 0][lm] = av.x; As[lk + 1][lm] = av.y;
        As[lk + 2][lm] = av.z; As[lk + 3][lm] = av.w;
        float4 bv = *(const float4*)&W[(n0 + lm) * ECC + k0 + lk];
        Bs[lk + 0][lm] = bv.x; Bs[lk + 1][lm] = bv.y;
        Bs[lk + 2][lm] = bv.z; Bs[lk + 3][lm] = bv.w;
        __syncthreads();

        #pragma unroll
        for (int kk = 0; kk < 16; kk++) {
            float a[4], b[4];
            *(float4*)a = *(const float4*)&As[kk][ty * 4];
            *(float4*)b = *(const float4*)&Bs[kk][tx * 4];
            #pragma unroll
            for (int i = 0; i < 4; i++)
                #pragma unroll
                for (int j = 0; j < 4; j++)
                    acc[i][j] = fmaf(a[i], b[j], acc[i][j]);
        }
        __syncthreads();
    }

    #pragma unroll
    for (int i = 0; i < 4; i++) {
        int m = m0 + ty * 4 + i;
        #pragma unroll
        for (int j = 0; j < 4; j++) {
            int n = n0 + tx * 4 + j;
            g_h1[m * Ec + n] = fmaxf(acc[i][j] + bias[n], 0.f);
        }
    }
}

// ---------------- softmax over RP1 per row ----------------
__global__ void __launch_bounds__(256)
k_softmax(const float* __restrict__ in)
{
    __shared__ float buf[RP1];
    __shared__ float red[256];
    int row = blockIdx.x, tid = threadIdx.x;
    const float* x = in + row * RP1;

    float mx = -1e30f;
    for (int j = tid; j < RP1; j += 256) {
        float v = x[j];
        buf[j] = v;
        mx = fmaxf(mx, v);
    }
    red[tid] = mx;
    __syncthreads();
    for (int s = 128; s > 0; s >>= 1) {
        if (tid < s) red[tid] = fmaxf(red[tid], red[tid + s]);
        __syncthreads();
    }
    mx = red[0];
    __syncthreads();

    float sm = 0.f;
    for (int j = tid; j < RP1; j += 256) {
        float e = __expf(buf[j] - mx);
        buf[j] = e;
        sm += e;
    }
    red[tid] = sm;
    __syncthreads();
    for (int s = 128; s > 0; s >>= 1) {
        if (tid < s) red[tid] += red[tid + s];
        __syncthreads();
    }
    float inv = 1.f / red[0];
    for (int j = tid; j < RP1; j += 256)
        g_sf[row * RP1 + j] = buf[j] * inv;
}

// ---------------- launch sequence ----------------
extern "C" void kernel_launch(void* const* d_in, const int* in_sizes, int n_in,
                              void* d_out, int out_size)
{
    const int*   bodys = (const int*)  d_in[0];
    const float* emb_w = (const float*)d_in[1];
    const float* w_ih  = (const float*)d_in[2];
    const float* w_hh  = (const float*)d_in[3];
    const float* b_ih  = (const float*)d_in[4];
    const float* b_hh  = (const float*)d_in[5];
    const float* fc1_w = (const float*)d_in[6];
    const float* fc1_b = (const float*)d_in[7];
    const float* fc2_w = (const float*)d_in[8];
    const float* fc2_b = (const float*)d_in[9];
    float* out = (float*)d_out;

    // Embed + init
    k_embed<<<(Bc * Lc * Ec) / 256, 256>>>(bodys, emb_w);
    k_init<<<(Bc * Ec) / 256, 256>>>(b_ih, b_hh);

    // LSTM: steps 0..6 only (step 7's hidden state is never consumed)
    for (int t = 0; t < Lc - 1; t++) {
        k_gates<<<dim3(G4 / BN, Bc / BM), 256>>>(t, w_ih, w_hh);
        k_lstm_point<<<(Bc * Ec) / 256, 256>>>(t);
    }

    // Autoregressive loop
    for (int i = 0; i < Lc - 1; i++) {
        if (i == 0) {
            k_ec0<<<(Bc * Ec) / 256, 256>>>();
        } else {
            k_nn2<<<dim3(Ec / TBN, Bc / TBM, NSPLIT), 256>>>(emb_w);
            k_nn_reduce<<<(Bc * Ec) / 256, 256>>>(i);
            k_ec_second<<<(Bc * Ec) / 256, 256>>>(emb_w, i);
        }
        // fc1: (B,512)@(512->256), relu+bias
        k_fc1<<<dim3(Ec / 64, Bc / 64), 256>>>(fc1_w, fc1_b);
        // fc2: (B,256)@(256->10001), bias, write directly into d_out
        k_fc2x2<<<dim3((RP1 + TBN - 1) / TBN, Bc / TBM), 256>>>(fc2_w, fc2_b, out);
        // softmax feeds the NEXT iteration; skip on the last one
        if (i < Lc - 2) k_softmax<<<Bc, 256>>>(out);
    }

    // emb_concat (final) appended after prob in d_out
    k_copy_ec<<<(Bc * ECC) / 256, 256>>>(out, out_size);
}

// round 15
// speedup vs baseline: 1.0438x; 1.0438x over previous
#include <cuda_runtime.h>
#include <cuda_bf16.h>
#include <math.h>

// Problem constants
#define Bc   1024
#define Lc   8
#define Ec   256
#define Rc   10000
#define RP1  10001
#define G4   1024       // 4*E
#define ECC  512        // 2*E

// fp32 gates tile config
#define BM 128
#define BN 128
#define BK 8
#define PAD 132

#define NSPLIT 16       // split-K for the NN mma gemm

// ---------------- scratch (device globals; no runtime allocation) ----------------
__device__ float g_x   [Bc * Lc * Ec];
__device__ float g_h   [Bc * Ec];
__device__ float g_c   [Bc * Ec];
__device__ float g_gates[Bc * G4];
__device__ float g_hid [Bc * Lc * Ec];
__device__ float g_ec  [Bc * ECC];
__device__ float g_part[NSPLIT * Bc * Ec];
__device__ float g_bias[G4];
__device__ float g_sflast[Bc];

// bf16 hi/lo planes
__device__ __nv_bfloat16 g_w2h[RP1 * Ec], g_w2l[RP1 * Ec];   // fc2_w
__device__ __nv_bfloat16 g_ewh[Rc * Ec],  g_ewl[Rc * Ec];    // emb_w
__device__ __nv_bfloat16 g_h1h[Bc * Ec],  g_h1l[Bc * Ec];    // fc1 out
__device__ __nv_bfloat16 g_sfh[Bc * Rc],  g_sfl[Bc * Rc];    // softmax out

// ---------------- mma helpers ----------------
__device__ __forceinline__ void ldm_x4(unsigned addr, unsigned& r0, unsigned& r1,
                                       unsigned& r2, unsigned& r3) {
    asm volatile("ldmatrix.sync.aligned.m8n8.x4.shared.b16 {%0,%1,%2,%3}, [%4];"
        : "=r"(r0), "=r"(r1), "=r"(r2), "=r"(r3) : "r"(addr));
}
__device__ __forceinline__ void ldm_x4t(unsigned addr, unsigned& r0, unsigned& r1,
                                        unsigned& r2, unsigned& r3) {
    asm volatile("ldmatrix.sync.aligned.m8n8.x4.trans.shared.b16 {%0,%1,%2,%3}, [%4];"
        : "=r"(r0), "=r"(r1), "=r"(r2), "=r"(r3) : "r"(addr));
}
__device__ __forceinline__ void mma_bf16(float* c, const unsigned* a,
                                         unsigned b0, unsigned b1) {
    asm volatile(
        "mma.sync.aligned.m16n8k16.row.col.f32.bf16.bf16.f32 "
        "{%0,%1,%2,%3}, {%4,%5,%6,%7}, {%8,%9}, {%0,%1,%2,%3};"
        : "+f"(c[0]), "+f"(c[1]), "+f"(c[2]), "+f"(c[3])
        : "r"(a[0]), "r"(a[1]), "r"(a[2]), "r"(a[3]), "r"(b0), "r"(b1));
}
__device__ __forceinline__ void split_bf16(float v, __nv_bfloat16& h, __nv_bfloat16& l) {
    h = __float2bfloat16(v);
    l = __float2bfloat16(v - __bfloat162float(h));
}

// ---------------- small kernels ----------------
__global__ void k_embed(const int* __restrict__ bodys, const float* __restrict__ emb_w) {
    int idx = blockIdx.x * 256 + threadIdx.x;
    if (idx < Bc * Lc * Ec) {
        int e  = idx & (Ec - 1);
        int bl = idx >> 8;
        g_x[idx] = emb_w[bodys[bl] * Ec + e];
    }
}

__global__ void k_init(const float* __restrict__ b_ih, const float* __restrict__ b_hh) {
    int idx = blockIdx.x * 256 + threadIdx.x;
    if (idx < G4) g_bias[idx] = b_ih[idx] + b_hh[idx];
    if (idx < Bc * Ec) { g_h[idx] = 0.f; g_c[idx] = 0.f; }
}

__global__ void k_prep_w2(const float* __restrict__ W) {
    int i = blockIdx.x * 256 + threadIdx.x;
    if (i < RP1 * Ec) split_bf16(W[i], g_w2h[i], g_w2l[i]);
}
__global__ void k_prep_ew(const float* __restrict__ W) {
    int i = blockIdx.x * 256 + threadIdx.x;
    if (i < Rc * Ec) split_bf16(W[i], g_ewh[i], g_ewl[i]);
}

__global__ void k_lstm_point(int t) {
    int idx = blockIdx.x * 256 + threadIdx.x;
    if (idx >= Bc * Ec) return;
    int b = idx >> 8, j = idx & (Ec - 1);
    const float* g = &g_gates[b * G4];
    float ig = 1.f / (1.f + __expf(-g[j]));
    float fg = 1.f / (1.f + __expf(-g[j + Ec]));
    float gg = tanhf(g[j + 2 * Ec]);
    float og = 1.f / (1.f + __expf(-g[j + 3 * Ec]));
    float c  = fg * g_c[idx] + ig * gg;
    float h  = og * tanhf(c);
    g_c[idx] = c;
    g_h[idx] = h;
    g_hid[(b * Lc + t) * Ec + j] = h;
}

__global__ void k_ec0() {
    int idx = blockIdx.x * 256 + threadIdx.x;
    if (idx >= Bc * Ec) return;
    int b = idx >> 8, e = idx & (Ec - 1);
    g_ec[b * ECC + e]      = g_x[(b * Lc + 0) * Ec + e];
    g_ec[b * ECC + Ec + e] = g_x[(b * Lc + 1) * Ec + e];
}

__global__ void k_ec_second(const float* __restrict__ emb_w, int i) {
    int idx = blockIdx.x * 256 + threadIdx.x;
    if (idx >= Bc * Ec) return;
    int b = idx >> 8, e = idx & (Ec - 1);
    g_ec[b * ECC + Ec + e] = emb_w[(i + 1) * Ec + e];
}

__global__ void k_nn_reduce(int i) {
    int idx = blockIdx.x * 256 + threadIdx.x;
    if (idx >= Bc * Ec) return;
    int b = idx >> 8, e = idx & (Ec - 1);
    float v = 0.f;
    #pragma unroll
    for (int s = 0; s < NSPLIT; s++) v += g_part[s * (Bc * Ec) + idx];
    v += g_sflast[b] * g_hid[(b * Lc + i) * Ec + e];
    g_ec[b * ECC + e] = v;
}

__global__ void k_copy_ec(float* __restrict__ out, int out_size) {
    int idx = blockIdx.x * 256 + threadIdx.x;
    if (idx >= Bc * ECC) return;
    int dst = Bc * RP1 + idx;
    if (dst < out_size) out[dst] = g_ec[idx];
}

// ================= fc2 via bf16-split tensor MMA =================
// out[m,n] = sum_k h1[m,k]*W[n,k] + bias[n];  M=1024, N=RP1, K=256
// Block tile 128x64, BK=16, 8 warps (2m x 4n), warp tile 64x16.
__global__ void __launch_bounds__(256, 2)
k_fc2_mma(const float* __restrict__ bias, float* __restrict__ out)
{
    __shared__ __align__(16) __nv_bfloat16 sAh[128 * 24], sAl[128 * 24];
    __shared__ __align__(16) __nv_bfloat16 sBh[64 * 24],  sBl[64 * 24];

    int tid = threadIdx.x;
    int m0 = blockIdx.y * 128, n0 = blockIdx.x * 64;
    int wid = tid >> 5, lane = tid & 31;
    int wm = (wid & 1) * 64, wn = (wid >> 1) * 16;
    int g = lane >> 2, qi = lane & 3;

    unsigned uAh = (unsigned)__cvta_generic_to_shared(sAh);
    unsigned uAl = (unsigned)__cvta_generic_to_shared(sAl);
    unsigned uBh = (unsigned)__cvta_generic_to_shared(sBh);
    unsigned uBl = (unsigned)__cvta_generic_to_shared(sBl);

    // ldmatrix lane addressing (byte offsets)
    int a_r = lane & 15, a_kh = lane >> 4;
    unsigned adA = (unsigned)((wm + a_r) * 24 + a_kh * 8) * 2;
    int b_nr = (lane & 7) + ((lane >> 4) << 3), b_kh = (lane >> 3) & 1;
    unsigned adB = (unsigned)((wn + b_nr) * 24 + b_kh * 8) * 2;

    // global load roles
    int arow = tid >> 1, ahalf = tid & 1;         // A: 128 rows x 2 halves
    int t2   = tid & 127;
    int brow = t2 >> 1, bhalf = t2 & 1;           // B: 64 rows x 2 halves
    int bn   = n0 + brow;
    bool bok = (bn < RP1);

    float acc[4][2][4];
    #pragma unroll
    for (int i = 0; i < 4; i++)
        #pragma unroll
        for (int j = 0; j < 2; j++)
            #pragma unroll
            for (int q = 0; q < 4; q++) acc[i][j][q] = 0.f;

    const int NK = Ec / 16;   // 16
    for (int kt = 0; kt < NK; kt++) {
        int k0 = kt * 16;
        uint4 vah = *(const uint4*)&g_h1h[(m0 + arow) * Ec + k0 + ahalf * 8];
        uint4 val = *(const uint4*)&g_h1l[(m0 + arow) * Ec + k0 + ahalf * 8];
        uint4 vb = make_uint4(0, 0, 0, 0);
        if (bok) {
            const __nv_bfloat16* src = (tid < 128) ? g_w2h : g_w2l;
            vb = *(const uint4*)&src[bn * Ec + k0 + bhalf * 8];
        }
        __syncthreads();   // previous stage's compute done
        *(uint4*)&sAh[arow * 24 + ahalf * 8] = vah;
        *(uint4*)&sAl[arow * 24 + ahalf * 8] = val;
        if (tid < 128) *(uint4*)&sBh[brow * 24 + bhalf * 8] = vb;
        else           *(uint4*)&sBl[brow * 24 + bhalf * 8] = vb;
        __syncthreads();

        unsigned ah[4][4], al[4][4], bh[4], bl[4];
        ldm_x4(uBh + adB, bh[0], bh[1], bh[2], bh[3]);
        ldm_x4(uBl + adB, bl[0], bl[1], bl[2], bl[3]);
        #pragma unroll
        for (int mi = 0; mi < 4; mi++) {
            unsigned off = adA + (unsigned)(mi * 16 * 24 * 2);
            ldm_x4(uAh + off, ah[mi][0], ah[mi][1], ah[mi][2], ah[mi][3]);
            ldm_x4(uAl + off, al[mi][0], al[mi][1], al[mi][2], al[mi][3]);
        }
        #pragma unroll
        for (int mi = 0; mi < 4; mi++)
            #pragma unroll
            for (int nj = 0; nj < 2; nj++) {
                mma_bf16(acc[mi][nj], ah[mi], bh[2 * nj], bh[2 * nj + 1]);
                mma_bf16(acc[mi][nj], al[mi], bh[2 * nj], bh[2 * nj + 1]);
                mma_bf16(acc[mi][nj], ah[mi], bl[2 * nj], bl[2 * nj + 1]);
            }
    }

    #pragma unroll
    for (int mi = 0; mi < 4; mi++) {
        int m = m0 + wm + mi * 16 + g;
        #pragma unroll
        for (int nj = 0; nj < 2; nj++) {
            int n = n0 + wn + nj * 8 + 2 * qi;
            if (n < RP1) {
                out[m * RP1 + n]       = acc[mi][nj][0] + bias[n];
                out[(m + 8) * RP1 + n] = acc[mi][nj][2] + bias[n];
            }
            if (n + 1 < RP1) {
                out[m * RP1 + n + 1]       = acc[mi][nj][1] + bias[n + 1];
                out[(m + 8) * RP1 + n + 1] = acc[mi][nj][3] + bias[n + 1];
            }
        }
    }
}

// ================= NN gemm via bf16-split tensor MMA (split-K) =================
// part[s][m,n] = sum_{k in split s} sf[m,k]*emb_w[k,n]; M=1024, N=256, K=10000
// A row-major bf16 planes (g_sfh/l); B = emb_w planes [k][n] via ldmatrix.trans.
__global__ void __launch_bounds__(256, 2)
k_nn_mma()
{
    __shared__ __align__(16) __nv_bfloat16 sAh[128 * 24], sAl[128 * 24];
    __shared__ __align__(16) __nv_bfloat16 sBh[16 * 72],  sBl[16 * 72];

    int tid = threadIdx.x;
    int n0 = blockIdx.x * 64, m0 = blockIdx.y * 128, sid = blockIdx.z;
    int wid = tid >> 5, lane = tid & 31;
    int wm = (wid & 1) * 64, wn = (wid >> 1) * 16;
    int g = lane >> 2, qi = lane & 3;

    unsigned uAh = (unsigned)__cvta_generic_to_shared(sAh);
    unsigned uAl = (unsigned)__cvta_generic_to_shared(sAl);
    unsigned uBh = (unsigned)__cvta_generic_to_shared(sBh);
    unsigned uBl = (unsigned)__cvta_generic_to_shared(sBl);

    int a_r = lane & 15, a_kh = lane >> 4;
    unsigned adA = (unsigned)((wm + a_r) * 24 + a_kh * 8) * 2;
    int bk_r = (lane & 7) + (lane & 8);          // 0..15
    int bnc  = (lane >> 4) * 8;                  // 0 or 8
    unsigned adB = (unsigned)(bk_r * 72 + wn + bnc) * 2;

    int arow = tid >> 1, ahalf = tid & 1;        // A loaders
    int t2   = tid & 127;
    int lkr  = t2 >> 3, lnc = t2 & 7;            // B loaders: 16 k-rows x 8 chunks

    const int KT_TOT = Rc / 16;                  // 625
    const int PER    = (KT_TOT + NSPLIT - 1) / NSPLIT;   // 40
    int kt0 = sid * PER;
    int kt1 = min(KT_TOT, kt0 + PER);

    float acc[4][2][4];
    #pragma unroll
    for (int i = 0; i < 4; i++)
        #pragma unroll
        for (int j = 0; j < 2; j++)
            #pragma unroll
            for (int q = 0; q < 4; q++) acc[i][j][q] = 0.f;

    for (int kt = kt0; kt < kt1; kt++) {
        int k0 = kt * 16;
        uint4 vah = *(const uint4*)&g_sfh[(m0 + arow) * Rc + k0 + ahalf * 8];
        uint4 val = *(const uint4*)&g_sfl[(m0 + arow) * Rc + k0 + ahalf * 8];
        const __nv_bfloat16* bsrc = (tid < 128) ? g_ewh : g_ewl;
        uint4 vb = *(const uint4*)&bsrc[(k0 + lkr) * Ec + n0 + lnc * 8];
        __syncthreads();
        *(uint4*)&sAh[arow * 24 + ahalf * 8] = vah;
        *(uint4*)&sAl[arow * 24 + ahalf * 8] = val;
        if (tid < 128) *(uint4*)&sBh[lkr * 72 + lnc * 8] = vb;
        else           *(uint4*)&sBl[lkr * 72 + lnc * 8] = vb;
        __syncthreads();

        unsigned ah[4][4], al[4][4], bh[4], bl[4];
        ldm_x4t(uBh + adB, bh[0], bh[1], bh[2], bh[3]);
        ldm_x4t(uBl + adB, bl[0], bl[1], bl[2], bl[3]);
        #pragma unroll
        for (int mi = 0; mi < 4; mi++) {
            unsigned off = adA + (unsigned)(mi * 16 * 24 * 2);
            ldm_x4(uAh + off, ah[mi][0], ah[mi][1], ah[mi][2], ah[mi][3]);
            ldm_x4(uAl + off, al[mi][0], al[mi][1], al[mi][2], al[mi][3]);
        }
        #pragma unroll
        for (int mi = 0; mi < 4; mi++)
            #pragma unroll
            for (int nj = 0; nj < 2; nj++) {
                mma_bf16(acc[mi][nj], ah[mi], bh[2 * nj], bh[2 * nj + 1]);
                mma_bf16(acc[mi][nj], al[mi], bh[2 * nj], bh[2 * nj + 1]);
                mma_bf16(acc[mi][nj], ah[mi], bl[2 * nj], bl[2 * nj + 1]);
            }
    }

    float* P = &g_part[sid * (Bc * Ec)];
    #pragma unroll
    for (int mi = 0; mi < 4; mi++) {
        int m = m0 + wm + mi * 16 + g;
        #pragma unroll
        for (int nj = 0; nj < 2; nj++) {
            int n = n0 + wn + nj * 8 + 2 * qi;
            *(float2*)&P[m * Ec + n]       = make_float2(acc[mi][nj][0], acc[mi][nj][1]);
            *(float2*)&P[(m + 8) * Ec + n] = make_float2(acc[mi][nj][2], acc[mi][nj][3]);
        }
    }
}

// ---------- Fused LSTM gates (proven fp32 128x128x8 kernel) ----------
__global__ void __launch_bounds__(256)
k_gates(int t, const float* __restrict__ w_ih, const float* __restrict__ w_hh)
{
    __shared__ float As[2][BK][PAD];
    __shared__ float Bs[2][BK][PAD];

    int tid  = threadIdx.x;
    int m0   = blockIdx.y * BM, n0 = blockIdx.x * BN;
    int arow = tid >> 1;
    int ac4  = (tid & 1) * 4;
    int tx   = tid & 15, ty = tid >> 4;

    const int NK = (2 * Ec) / BK;       // 64

    auto fetch = [&](int kt, float4& pa, float4& pb) {
        if (kt < 32) {
            int k0 = kt * BK;
            pa = *(const float4*)&g_x[(m0 + arow) * (Lc * Ec) + t * Ec + k0 + ac4];
            pb = *(const float4*)&w_ih[(n0 + arow) * Ec + k0 + ac4];
        } else {
            int k0 = (kt - 32) * BK;
            pa = *(const float4*)&g_h[(m0 + arow) * Ec + k0 + ac4];
            pb = *(const float4*)&w_hh[(n0 + arow) * Ec + k0 + ac4];
        }
    };

    float4 pa, pb;
    fetch(0, pa, pb);
    As[0][ac4 + 0][arow] = pa.x; As[0][ac4 + 1][arow] = pa.y;
    As[0][ac4 + 2][arow] = pa.z; As[0][ac4 + 3][arow] = pa.w;
    Bs[0][ac4 + 0][arow] = pb.x; Bs[0][ac4 + 1][arow] = pb.y;
    Bs[0][ac4 + 2][arow] = pb.z; Bs[0][ac4 + 3][arow] = pb.w;
    __syncthreads();

    float acc[8][8] = {};
    int buf = 0;
    for (int kt = 0; kt < NK; kt++) {
        if (kt + 1 < NK) fetch(kt + 1, pa, pb);
        #pragma unroll
        for (int kk = 0; kk < BK; kk++) {
            float a[8], b[8];
            *(float4*)&a[0] = *(const float4*)&As[buf][kk][ty * 8];
            *(float4*)&a[4] = *(const float4*)&As[buf][kk][ty * 8 + 4];
            *(float4*)&b[0] = *(const float4*)&Bs[buf][kk][tx * 8];
            *(float4*)&b[4] = *(const float4*)&Bs[buf][kk][tx * 8 + 4];
            #pragma unroll
            for (int i = 0; i < 8; i++)
                #pragma unroll
                for (int j = 0; j < 8; j++)
                    acc[i][j] = fmaf(a[i], b[j], acc[i][j]);
        }
        if (kt + 1 < NK) {
            int nb = buf ^ 1;
            As[nb][ac4 + 0][arow] = pa.x; As[nb][ac4 + 1][arow] = pa.y;
            As[nb][ac4 + 2][arow] = pa.z; As[nb][ac4 + 3][arow] = pa.w;
            Bs[nb][ac4 + 0][arow] = pb.x; Bs[nb][ac4 + 1][arow] = pb.y;
            Bs[nb][ac4 + 2][arow] = pb.z; Bs[nb][ac4 + 3][arow] = pb.w;
        }
        __syncthreads();
        buf ^= 1;
    }

    #pragma unroll
    for (int i = 0; i < 8; i++) {
        int m = m0 + ty * 8 + i;
        #pragma unroll
        for (int j = 0; j < 8; j++) {
            int n = n0 + tx * 8 + j;
            g_gates[m * G4 + n] = acc[i][j] + g_bias[n];
        }
    }
}

// ---------------- fc1: 64x64x16 NT GEMM, writes bf16 hi/lo planes ----------------
__global__ void __launch_bounds__(256)
k_fc1(const float* __restrict__ W, const float* __restrict__ bias)
{
    __shared__ float As[16][64];
    __shared__ float Bs[16][64];

    int tid = threadIdx.x;
    int tx = tid & 15, ty = tid >> 4;
    int m0 = blockIdx.y * 64, n0 = blockIdx.x * 64;

    int lm = tid >> 2;
    int lk = (tid & 3) * 4;

    float acc[4][4] = {};

    for (int k0 = 0; k0 < ECC; k0 += 16) {
        float4 av = *(const float4*)&g_ec[(m0 + lm) * ECC + k0 + lk];
        As[lk + 0][lm] = av.x; As[lk + 1][lm] = av.y;
        As[lk + 2][lm] = av.z; As[lk + 3][lm] = av.w;
        float4 bv = *(const float4*)&W[(n0 + lm) * ECC + k0 + lk];
        Bs[lk + 0][lm] = bv.x; Bs[lk + 1][lm] = bv.y;
        Bs[lk + 2][lm] = bv.z; Bs[lk + 3][lm] = bv.w;
        __syncthreads();

        #pragma unroll
        for (int kk = 0; kk < 16; kk++) {
            float a[4], b[4];
            *(float4*)a = *(const float4*)&As[kk][ty * 4];
            *(float4*)b = *(const float4*)&Bs[kk][tx * 4];
            #pragma unroll
            for (int i = 0; i < 4; i++)
                #pragma unroll
                for (int j = 0; j < 4; j++)
                    acc[i][j] = fmaf(a[i], b[j], acc[i][j]);
        }
        __syncthreads();
    }

    #pragma unroll
    for (int i = 0; i < 4; i++) {
        int m = m0 + ty * 4 + i;
        #pragma unroll
        for (int j = 0; j < 4; j++) {
            int n = n0 + tx * 4 + j;
            float v = fmaxf(acc[i][j] + bias[n], 0.f);
            __nv_bfloat16 h, l;
            split_bf16(v, h, l);
            g_h1h[m * Ec + n] = h;
            g_h1l[m * Ec + n] = l;
        }
    }
}

// ---------------- softmax over RP1 per row; emits bf16 hi/lo planes ----------
__global__ void __launch_bounds__(256)
k_softmax(const float* __restrict__ in)
{
    __shared__ float buf[RP1];
    __shared__ float red[256];
    int row = blockIdx.x, tid = threadIdx.x;
    const float* x = in + row * RP1;

    float mx = -1e30f;
    for (int j = tid; j < RP1; j += 256) {
        float v = x[j];
        buf[j] = v;
        mx = fmaxf(mx, v);
    }
    red[tid] = mx;
    __syncthreads();
    for (int s = 128; s > 0; s >>= 1) {
        if (tid < s) red[tid] = fmaxf(red[tid], red[tid + s]);
        __syncthreads();
    }
    mx = red[0];
    __syncthreads();

    float sm = 0.f;
    for (int j = tid; j < RP1; j += 256) {
        float e = __expf(buf[j] - mx);
        buf[j] = e;
        sm += e;
    }
    red[tid] = sm;
    __syncthreads();
    for (int s = 128; s > 0; s >>= 1) {
        if (tid < s) red[tid] += red[tid + s];
        __syncthreads();
    }
    float inv = 1.f / red[0];
    for (int j = tid; j < RP1; j += 256) {
        float v = buf[j] * inv;
        if (j < Rc) {
            __nv_bfloat16 h, l;
            split_bf16(v, h, l);
            g_sfh[row * Rc + j] = h;
            g_sfl[row * Rc + j] = l;
        } else {
            g_sflast[row] = v;
        }
    }
}

// ---------------- launch sequence ----------------
extern "C" void kernel_launch(void* const* d_in, const int* in_sizes, int n_in,
                              void* d_out, int out_size)
{
    const int*   bodys = (const int*)  d_in[0];
    const float* emb_w = (const float*)d_in[1];
    const float* w_ih  = (const float*)d_in[2];
    const float* w_hh  = (const float*)d_in[3];
    const float* b_ih  = (const float*)d_in[4];
    const float* b_hh  = (const float*)d_in[5];
    const float* fc1_w = (const float*)d_in[6];
    const float* fc1_b = (const float*)d_in[7];
    const float* fc2_w = (const float*)d_in[8];
    const float* fc2_b = (const float*)d_in[9];
    float* out = (float*)d_out;

    // Embed + init + weight bf16 split
    k_embed<<<(Bc * Lc * Ec) / 256, 256>>>(bodys, emb_w);
    k_init<<<(Bc * Ec) / 256, 256>>>(b_ih, b_hh);
    k_prep_w2<<<(RP1 * Ec + 255) / 256, 256>>>(fc2_w);
    k_prep_ew<<<(Rc * Ec + 255) / 256, 256>>>(emb_w);

    // LSTM: steps 0..6 only (step 7's hidden state is never consumed)
    for (int t = 0; t < Lc - 1; t++) {
        k_gates<<<dim3(G4 / BN, Bc / BM), 256>>>(t, w_ih, w_hh);
        k_lstm_point<<<(Bc * Ec) / 256, 256>>>(t);
    }

    // Autoregressive loop
    for (int i = 0; i < Lc - 1; i++) {
        if (i == 0) {
            k_ec0<<<(Bc * Ec) / 256, 256>>>();
        } else {
            k_nn_mma<<<dim3(Ec / 64, Bc / 128, NSPLIT), 256>>>();
            k_nn_reduce<<<(Bc * Ec) / 256, 256>>>(i);
            k_ec_second<<<(Bc * Ec) / 256, 256>>>(emb_w, i);
        }
        // fc1: (B,512)@(512->256), relu+bias, emits bf16 hi/lo
        k_fc1<<<dim3(Ec / 64, Bc / 64), 256>>>(fc1_w, fc1_b);
        // fc2 on tensor cores: (B,256)@(256->10001), bias, write into d_out
        k_fc2_mma<<<dim3((RP1 + 63) / 64, Bc / 128), 256>>>(fc2_b, out);
        // softmax feeds the NEXT iteration; skip on the last one
        if (i < Lc - 2) k_softmax<<<Bc, 256>>>(out);
    }

    // emb_concat (final) appended after prob in d_out
    k_copy_ec<<<(Bc * ECC) / 256, 256>>>(out, out_size);
}